// round 1
// baseline (speedup 1.0000x reference)
#include <cuda_runtime.h>
#include <math.h>

#define NP 50000
#define NPAD 50048          // 782 * 64
#define D 128
#define NE 800000
#define EA (2*NE + NP)      // 1,650,000 augmented edges
#define BB 512
#define LL 64
#define NH 4
#define HD 32

// ---------------- scratch (device globals; no allocations) ----------------
__device__ float g_deg[NP];
__device__ int   g_ptr[NP+1];
__device__ int   g_fill[NP];
__device__ int   g_dst[EA];
__device__ float g_w[EA];
__device__ float g_enc0[NPAD*D];
__device__ float g_enc1[NPAD*D];
__device__ float g_agg[NPAD*D];
__device__ float g_sumw[NPAD];
__device__ float g_qkv[BB*LL*3*D];
__device__ float g_obar[BB*D];

// ---------------- graph prep ----------------
__global__ void k_init() {
    int i = blockIdx.x*blockDim.x + threadIdx.x;
    if (i < NP) { g_deg[i] = 1.0f; g_fill[i] = 0; }   // 1.0 = self loop
}

__global__ void k_deg(const int* __restrict__ edges) {
    int e = blockIdx.x*blockDim.x + threadIdx.x;
    if (e < NE) {
        atomicAdd(&g_deg[edges[e]],      1.0f);   // src (original edge)
        atomicAdd(&g_deg[edges[NE+e]],   1.0f);   // dst (as src of reversed edge)
    }
}

// single-block exclusive scan of (int)deg -> csr ptr
__global__ void k_scan() {
    __shared__ int wsum[32];
    int tid = threadIdx.x;
    const int per = (NP + 1023)/1024;  // 49
    int beg = tid*per;
    int end = min(beg+per, NP);
    int s = 0;
    for (int i=beg;i<end;i++) s += (int)g_deg[i];
    int lane = tid & 31, wid = tid >> 5;
    int v = s;
    #pragma unroll
    for (int o=1;o<32;o<<=1){ int t=__shfl_up_sync(0xffffffffu,v,o); if(lane>=o) v+=t; }
    if (lane==31) wsum[wid]=v;
    __syncthreads();
    if (wid==0){
        int t = wsum[lane];
        #pragma unroll
        for (int o=1;o<32;o<<=1){ int u=__shfl_up_sync(0xffffffffu,t,o); if(lane>=o) t+=u; }
        wsum[lane]=t;
    }
    __syncthreads();
    int excl = v - s + (wid>0 ? wsum[wid-1] : 0);
    int run = excl;
    for (int i=beg;i<end;i++){ g_ptr[i]=run; run += (int)g_deg[i]; }
    if (end == NP) g_ptr[NP] = run;   // threads past the data all hold run==total
}

__global__ void k_fill(const int* __restrict__ edges, const float* __restrict__ dvec) {
    int e = blockIdx.x*blockDim.x + threadIdx.x;
    if (e >= EA) return;
    int s, d; float dv;
    if (e < NE)          { s = edges[e];       d = edges[NE+e];   dv = dvec[e];   }
    else if (e < 2*NE)   { int e2 = e - NE; s = edges[NE+e2]; d = edges[e2]; dv = dvec[e2]; }
    else                 { s = d = e - 2*NE; dv = 0.f; }
    float wv = rsqrtf(g_deg[s]*g_deg[d]) * expf(-dv*dv);
    int pos = atomicAdd(&g_fill[s], 1);
    int idx = g_ptr[s] + pos;
    g_dst[idx] = d;
    g_w[idx]   = wv;
}

// ---------------- GNN layer: aggregate raw enc (warp per node) ----------------
__global__ void k_agg(const float* __restrict__ enc) {
    int warp = (blockIdx.x*blockDim.x + threadIdx.x) >> 5;
    int lane = threadIdx.x & 31;
    if (warp >= NP) return;
    int beg = g_ptr[warp], end = g_ptr[warp+1];
    float4 acc = make_float4(0.f,0.f,0.f,0.f);
    float sw = 0.f;
    for (int i = beg; i < end; i++) {
        int   d  = g_dst[i];
        float wv = g_w[i];
        float4 v = *(const float4*)(enc + (size_t)d*D + lane*4);
        acc.x += wv*v.x; acc.y += wv*v.y; acc.z += wv*v.z; acc.w += wv*v.w;
        sw += wv;
    }
    *(float4*)(g_agg + (size_t)warp*D + lane*4) = acc;
    if (lane == 0) g_sumw[warp] = sw;
}

// ---------------- fused linear + leaky + L2-normalize ----------------
// out[n,r] = normalize( leaky( sum_k W[r,k]*agg[n,k] + b[r]*sumw[n] ) )
__global__ void k_lin(const float* __restrict__ W, const float* __restrict__ bias,
                      float* __restrict__ out) {
    __shared__ float As[16][64];
    __shared__ float Ws[16][128];
    int tid = threadIdx.x;       // 256
    int tr = tid >> 5;           // warp id 0..7  -> rows tr*8 .. tr*8+7
    int tc = tid & 31;           // lane          -> cols tc*4 .. tc*4+3
    int rb = blockIdx.x * 64;
    float acc[8][4];
    #pragma unroll
    for (int i=0;i<8;i++)
        #pragma unroll
        for (int j=0;j<4;j++) acc[i][j]=0.f;

    for (int k0=0;k0<128;k0+=16) {
        {
            int m  = tid & 63;
            int kk = (tid >> 6) << 2;
            float4 v = *(const float4*)(g_agg + (size_t)(rb+m)*D + k0 + kk);
            As[kk][m]=v.x; As[kk+1][m]=v.y; As[kk+2][m]=v.z; As[kk+3][m]=v.w;
        }
        {
            int n  = tid & 127;
            int kk = (tid >> 7) << 3;
            float4 v  = *(const float4*)(W + (size_t)n*D + k0 + kk);
            Ws[kk  ][n]=v.x;  Ws[kk+1][n]=v.y;  Ws[kk+2][n]=v.z;  Ws[kk+3][n]=v.w;
            float4 v2 = *(const float4*)(W + (size_t)n*D + k0 + kk + 4);
            Ws[kk+4][n]=v2.x; Ws[kk+5][n]=v2.y; Ws[kk+6][n]=v2.z; Ws[kk+7][n]=v2.w;
        }
        __syncthreads();
        #pragma unroll
        for (int kk=0;kk<16;kk++) {
            float4 a0 = *(const float4*)&As[kk][tr*8];
            float4 a1 = *(const float4*)&As[kk][tr*8+4];
            float4 w4 = *(const float4*)&Ws[kk][tc*4];
            float a[8] = {a0.x,a0.y,a0.z,a0.w,a1.x,a1.y,a1.z,a1.w};
            float w[4] = {w4.x,w4.y,w4.z,w4.w};
            #pragma unroll
            for (int i=0;i<8;i++)
                #pragma unroll
                for (int j=0;j<4;j++)
                    acc[i][j] += a[i]*w[j];
        }
        __syncthreads();
    }
    // epilogue: bias*sumw, leaky, row L2-normalize (whole row lives in this warp)
    #pragma unroll
    for (int i=0;i<8;i++) {
        int row = rb + tr*8 + i;
        float sw = g_sumw[row];
        float ss = 0.f;
        #pragma unroll
        for (int j=0;j<4;j++) {
            float v = acc[i][j] + bias[tc*4+j]*sw;
            v = (v >= 0.f) ? v : 0.01f*v;
            acc[i][j] = v;
            ss += v*v;
        }
        #pragma unroll
        for (int o=16;o>0;o>>=1) ss += __shfl_xor_sync(0xffffffffu, ss, o);
        float inv = 1.0f / fmaxf(sqrtf(ss), 1e-12f);
        if (row < NP) {
            float4 o4 = make_float4(acc[i][0]*inv, acc[i][1]*inv, acc[i][2]*inv, acc[i][3]*inv);
            *(float4*)(out + (size_t)row*D + tc*4) = o4;
        }
    }
}

// ---------------- qkv projection with fused gather ----------------
__global__ void k_qkv(const int* __restrict__ idx,
                      const float* __restrict__ W, const float* __restrict__ bias) {
    __shared__ float As[16][64];
    __shared__ float Ws[16][128];
    __shared__ int ridx[64];
    int tid = threadIdx.x;
    int tr = tid >> 5, tc = tid & 31;
    int rb = blockIdx.x * 64;        // 512 blocks  (M = 32768)
    int nb = blockIdx.y * 128;       // 3 blocks    (N = 384)
    if (tid < 64) ridx[tid] = idx[rb + tid];
    __syncthreads();
    float acc[8][4];
    #pragma unroll
    for (int i=0;i<8;i++)
        #pragma unroll
        for (int j=0;j<4;j++) acc[i][j]=0.f;

    for (int k0=0;k0<128;k0+=16) {
        {
            int m  = tid & 63;
            int kk = (tid >> 6) << 2;
            float4 v = *(const float4*)(g_enc1 + (size_t)ridx[m]*D + k0 + kk);
            As[kk][m]=v.x; As[kk+1][m]=v.y; As[kk+2][m]=v.z; As[kk+3][m]=v.w;
        }
        {
            int n  = tid & 127;
            int kk = (tid >> 7) << 3;
            float4 v  = *(const float4*)(W + (size_t)(nb+n)*D + k0 + kk);
            Ws[kk  ][n]=v.x;  Ws[kk+1][n]=v.y;  Ws[kk+2][n]=v.z;  Ws[kk+3][n]=v.w;
            float4 v2 = *(const float4*)(W + (size_t)(nb+n)*D + k0 + kk + 4);
            Ws[kk+4][n]=v2.x; Ws[kk+5][n]=v2.y; Ws[kk+6][n]=v2.z; Ws[kk+7][n]=v2.w;
        }
        __syncthreads();
        #pragma unroll
        for (int kk=0;kk<16;kk++) {
            float4 a0 = *(const float4*)&As[kk][tr*8];
            float4 a1 = *(const float4*)&As[kk][tr*8+4];
            float4 w4 = *(const float4*)&Ws[kk][tc*4];
            float a[8] = {a0.x,a0.y,a0.z,a0.w,a1.x,a1.y,a1.z,a1.w};
            float w[4] = {w4.x,w4.y,w4.z,w4.w};
            #pragma unroll
            for (int i=0;i<8;i++)
                #pragma unroll
                for (int j=0;j<4;j++)
                    acc[i][j] += a[i]*w[j];
        }
        __syncthreads();
    }
    #pragma unroll
    for (int i=0;i<8;i++) {
        int row = rb + tr*8 + i;
        int c   = nb + tc*4;
        float4 o4 = make_float4(acc[i][0]+bias[c], acc[i][1]+bias[c+1],
                                acc[i][2]+bias[c+2], acc[i][3]+bias[c+3]);
        *(float4*)(g_qkv + (size_t)row*(3*D) + c) = o4;
    }
}

// ---------------- attention per (b,h); mean-over-L folded into pbar matvec ----------------
__global__ void k_attn() {
    __shared__ float ks[64][32];
    __shared__ float vs[64][32];
    __shared__ float ps[64][65];     // padded: conflict-free column access
    __shared__ float pbar[64];
    int b = blockIdx.x, h = blockIdx.y;
    int tid = threadIdx.x;           // 256
    for (int t = tid; t < 512; t += 256) {
        int l = t >> 3, c4 = (t & 7) << 2;
        const float* base = g_qkv + (size_t)(b*LL + l)*(3*D) + h*HD + c4;
        *(float4*)&ks[l][c4] = *(const float4*)(base + 128);
        *(float4*)&vs[l][c4] = *(const float4*)(base + 256);
    }
    __syncthreads();
    {
        int i  = tid & 63;
        int jg = tid >> 6;
        float4 q[8];
        const float* qb = g_qkv + (size_t)(b*LL + i)*(3*D) + h*HD;
        #pragma unroll
        for (int u=0;u<8;u++) q[u] = *(const float4*)(qb + 4*u);
        const float scale = 0.17677669529663687f;   // 1/sqrt(32)
        #pragma unroll
        for (int jj=0;jj<16;jj++) {
            int j = jg*16 + jj;                      // warp-uniform j -> smem broadcast
            float s = 0.f;
            #pragma unroll
            for (int u=0;u<8;u++) {
                float4 kv = *(const float4*)&ks[j][4*u];
                s += q[u].x*kv.x + q[u].y*kv.y + q[u].z*kv.z + q[u].w*kv.w;
            }
            ps[i][j] = s * scale;
        }
    }
    __syncthreads();
    if (tid < 64) {
        int i = tid;
        float mx = -1e30f;
        for (int j=0;j<64;j++) mx = fmaxf(mx, ps[i][j]);
        float sum = 0.f;
        for (int j=0;j<64;j++) { float e = expf(ps[i][j]-mx); ps[i][j]=e; sum+=e; }
        float inv = 1.0f/sum;
        for (int j=0;j<64;j++) ps[i][j] *= inv;
    }
    __syncthreads();
    if (tid < 64) {
        int j = tid;
        float s = 0.f;
        for (int i=0;i<64;i++) s += ps[i][j];
        pbar[j] = s * (1.0f/64.0f);
    }
    __syncthreads();
    if (tid < 32) {
        int c = tid;
        float s = 0.f;
        #pragma unroll 4
        for (int j=0;j<64;j++) s += pbar[j]*vs[j][c];
        g_obar[(size_t)b*D + h*HD + c] = s;
    }
}

// ---------------- out-proj (after mean) + tar_embed gather ----------------
__global__ void k_out(const int* __restrict__ data_poi,
                      const float* __restrict__ Wo, const float* __restrict__ bo,
                      float* __restrict__ out) {
    __shared__ float ob[128];
    int b = blockIdx.x, r = threadIdx.x;   // 128 threads
    ob[r] = g_obar[(size_t)b*D + r];
    __syncthreads();
    float acc = bo[r];
    const float* wr = Wo + (size_t)r*D;
    #pragma unroll 8
    for (int k=0;k<D;k++) acc += ob[k]*wr[k];
    out[(size_t)b*D + r] = acc;            // aggr_feat
    int p = data_poi[b];
    out[(size_t)BB*D + (size_t)b*D + r] = g_enc1[(size_t)p*D + r];   // tar_embed
}

// ---------------- launch ----------------
extern "C" void kernel_launch(void* const* d_in, const int* in_sizes, int n_in,
                              void* d_out, int out_size) {
    const float* poi_embeds = (const float*)d_in[0];
    const int*   edges      = (const int*)  d_in[1];   // [2, NE] row-major
    const float* dvec       = (const float*)d_in[2];
    const int*   data_poi   = (const int*)  d_in[3];
    const int*   data_x     = (const int*)  d_in[4];
    const float* lin_w      = (const float*)d_in[5];   // [2,128,128]
    const float* lin_b      = (const float*)d_in[6];   // [2,128]
    const float* in_w       = (const float*)d_in[7];   // [384,128]
    const float* in_b       = (const float*)d_in[8];
    const float* out_w      = (const float*)d_in[9];   // [128,128]
    const float* out_b      = (const float*)d_in[10];
    float* out = (float*)d_out;

    float *p_enc0, *p_enc1;
    cudaGetSymbolAddress((void**)&p_enc0, g_enc0);
    cudaGetSymbolAddress((void**)&p_enc1, g_enc1);

    k_init<<<(NP+255)/256, 256>>>();
    k_deg <<<(NE+255)/256, 256>>>(edges);
    k_scan<<<1, 1024>>>();
    k_fill<<<(EA+255)/256, 256>>>(edges, dvec);

    // layer 0
    k_agg<<<(NP*32+255)/256, 256>>>(poi_embeds);
    k_lin<<<NPAD/64, 256>>>(lin_w, lin_b, p_enc0);
    // layer 1
    k_agg<<<(NP*32+255)/256, 256>>>(p_enc0);
    k_lin<<<NPAD/64, 256>>>(lin_w + D*D, lin_b + D, p_enc1);

    // attention block
    k_qkv<<<dim3(512,3), 256>>>(data_x, in_w, in_b);
    k_attn<<<dim3(BB, NH), 256>>>();
    k_out<<<BB, 128>>>(data_poi, out_w, out_b, out);
}

// round 2
// speedup vs baseline: 1.0518x; 1.0518x over previous
#include <cuda_runtime.h>
#include <cuda_fp16.h>
#include <math.h>

#define NP 50000
#define NPAD 50048          // 782 * 64
#define D 128
#define NE 800000
#define EC (2*NE)           // CSR entries (self loops handled analytically)
#define BB 512
#define LL 64
#define NH 4
#define HD 32

// ---------------- scratch (device globals; no allocations) ----------------
__device__ float  g_deg[NP];
__device__ int    g_ptr[NP+1];
__device__ int    g_fill[NP];
__device__ int    g_dst[EC];
__device__ float  g_w[EC];
__device__ __half g_ench[NPAD*D];   // fp16 gather operand (poi, then enc0)
__device__ float  g_enc1[NPAD*D];   // final encoder output (fp32: feeds outputs)
__device__ float  g_agg[NPAD*D];
__device__ float  g_sumw[NPAD];
__device__ float  g_qkv[BB*LL*3*D];
__device__ float  g_obar[BB*D];

// ---------------- graph prep ----------------
__global__ void k_init() {
    int i = blockIdx.x*blockDim.x + threadIdx.x;
    if (i < NP) { g_deg[i] = 1.0f; g_fill[i] = 0; }   // 1.0 = self loop
}

__global__ void k_deg(const int* __restrict__ edges) {
    int e = blockIdx.x*blockDim.x + threadIdx.x;
    if (e < NE) {
        atomicAdd(&g_deg[edges[e]],    1.0f);
        atomicAdd(&g_deg[edges[NE+e]], 1.0f);
    }
}

// single-block exclusive scan of (deg-1) -> csr ptr (self loops not stored)
__global__ void k_scan() {
    __shared__ int wsum[32];
    int tid = threadIdx.x;
    const int per = (NP + 1023)/1024;  // 49
    int beg = tid*per;
    int end = min(beg+per, NP);
    int s = 0;
    for (int i=beg;i<end;i++) s += (int)g_deg[i] - 1;
    int lane = tid & 31, wid = tid >> 5;
    int v = s;
    #pragma unroll
    for (int o=1;o<32;o<<=1){ int t=__shfl_up_sync(0xffffffffu,v,o); if(lane>=o) v+=t; }
    if (lane==31) wsum[wid]=v;
    __syncthreads();
    if (wid==0){
        int t = wsum[lane];
        #pragma unroll
        for (int o=1;o<32;o<<=1){ int u=__shfl_up_sync(0xffffffffu,t,o); if(lane>=o) t+=u; }
        wsum[lane]=t;
    }
    __syncthreads();
    int excl = v - s + (wid>0 ? wsum[wid-1] : 0);
    int run = excl;
    for (int i=beg;i<end;i++){ g_ptr[i]=run; run += (int)g_deg[i] - 1; }
    if (end == NP) g_ptr[NP] = run;
}

// one thread per ORIGINAL edge: w is symmetric -> fill both directions
__global__ void k_fill(const int* __restrict__ edges, const float* __restrict__ dvec) {
    int e = blockIdx.x*blockDim.x + threadIdx.x;
    if (e >= NE) return;
    int s = edges[e], d = edges[NE+e];
    float dv = dvec[e];
    float wv = rsqrtf(g_deg[s]*g_deg[d]) * expf(-dv*dv);
    int p1 = atomicAdd(&g_fill[s], 1);
    int i1 = g_ptr[s] + p1;
    g_dst[i1] = d;  g_w[i1] = wv;
    int p2 = atomicAdd(&g_fill[d], 1);
    int i2 = g_ptr[d] + p2;
    g_dst[i2] = s;  g_w[i2] = wv;
}

// fp32 -> fp16 convert (poi embeddings)
__global__ void k_cvt(const float* __restrict__ x, __half* __restrict__ y) {
    int i = (blockIdx.x*blockDim.x + threadIdx.x) * 4;
    if (i < NP*D) {
        float4 v = *(const float4*)(x + i);
        __half2 a = __floats2half2_rn(v.x, v.y);
        __half2 b = __floats2half2_rn(v.z, v.w);
        uint2 o; o.x = *(unsigned*)&a; o.y = *(unsigned*)&b;
        *(uint2*)(y + i) = o;
    }
}

// ---------------- GNN layer: aggregate fp16 enc (warp per node), fp32 accum ----------------
__global__ void k_agg(const __half* __restrict__ enc) {
    int warp = (blockIdx.x*blockDim.x + threadIdx.x) >> 5;
    int lane = threadIdx.x & 31;
    if (warp >= NP) return;
    int beg = g_ptr[warp], end = g_ptr[warp+1];
    // self loop: w = rsqrt(deg*deg)*exp(0) = 1/deg
    float wself = 1.0f / g_deg[warp];
    uint2 sv = *(const uint2*)(enc + (size_t)warp*D + lane*4);
    float2 fa = __half22float2(*(const __half2*)&sv.x);
    float2 fb = __half22float2(*(const __half2*)&sv.y);
    float4 acc = make_float4(wself*fa.x, wself*fa.y, wself*fb.x, wself*fb.y);
    float sw = wself;
    for (int i = beg; i < end; i++) {
        int   d  = __ldg(&g_dst[i]);
        float wv = __ldg(&g_w[i]);
        uint2 v  = *(const uint2*)(enc + (size_t)d*D + lane*4);
        float2 va = __half22float2(*(const __half2*)&v.x);
        float2 vb = __half22float2(*(const __half2*)&v.y);
        acc.x += wv*va.x; acc.y += wv*va.y; acc.z += wv*vb.x; acc.w += wv*vb.y;
        sw += wv;
    }
    *(float4*)(g_agg + (size_t)warp*D + lane*4) = acc;
    if (lane == 0) g_sumw[warp] = sw;
}

// ---------------- fused linear + leaky + L2-normalize ----------------
// out[n,r] = normalize( leaky( sum_k W[r,k]*agg[n,k] + b[r]*sumw[n] ) )
// writes fp16 (outH) and/or fp32 (outF)
__global__ void k_lin(const float* __restrict__ W, const float* __restrict__ bias,
                      float* __restrict__ outF, __half* __restrict__ outH) {
    __shared__ float As[16][64];
    __shared__ float Ws[16][128];
    int tid = threadIdx.x;       // 256
    int tr = tid >> 5;           // warp id 0..7  -> rows tr*8 .. tr*8+7
    int tc = tid & 31;           // lane          -> cols tc*4 .. tc*4+3
    int rb = blockIdx.x * 64;
    float acc[8][4];
    #pragma unroll
    for (int i=0;i<8;i++)
        #pragma unroll
        for (int j=0;j<4;j++) acc[i][j]=0.f;

    for (int k0=0;k0<128;k0+=16) {
        {
            int m  = tid & 63;
            int kk = (tid >> 6) << 2;
            float4 v = *(const float4*)(g_agg + (size_t)(rb+m)*D + k0 + kk);
            As[kk][m]=v.x; As[kk+1][m]=v.y; As[kk+2][m]=v.z; As[kk+3][m]=v.w;
        }
        {
            int n  = tid & 127;
            int kk = (tid >> 7) << 3;
            float4 v  = *(const float4*)(W + (size_t)n*D + k0 + kk);
            Ws[kk  ][n]=v.x;  Ws[kk+1][n]=v.y;  Ws[kk+2][n]=v.z;  Ws[kk+3][n]=v.w;
            float4 v2 = *(const float4*)(W + (size_t)n*D + k0 + kk + 4);
            Ws[kk+4][n]=v2.x; Ws[kk+5][n]=v2.y; Ws[kk+6][n]=v2.z; Ws[kk+7][n]=v2.w;
        }
        __syncthreads();
        #pragma unroll
        for (int kk=0;kk<16;kk++) {
            float4 a0 = *(const float4*)&As[kk][tr*8];
            float4 a1 = *(const float4*)&As[kk][tr*8+4];
            float4 w4 = *(const float4*)&Ws[kk][tc*4];
            float a[8] = {a0.x,a0.y,a0.z,a0.w,a1.x,a1.y,a1.z,a1.w};
            float w[4] = {w4.x,w4.y,w4.z,w4.w};
            #pragma unroll
            for (int i=0;i<8;i++)
                #pragma unroll
                for (int j=0;j<4;j++)
                    acc[i][j] += a[i]*w[j];
        }
        __syncthreads();
    }
    // epilogue: bias*sumw, leaky, row L2-normalize (whole row lives in this warp)
    #pragma unroll
    for (int i=0;i<8;i++) {
        int row = rb + tr*8 + i;
        float sw = g_sumw[row];
        float ss = 0.f;
        #pragma unroll
        for (int j=0;j<4;j++) {
            float v = acc[i][j] + bias[tc*4+j]*sw;
            v = (v >= 0.f) ? v : 0.01f*v;
            acc[i][j] = v;
            ss += v*v;
        }
        #pragma unroll
        for (int o=16;o>0;o>>=1) ss += __shfl_xor_sync(0xffffffffu, ss, o);
        float inv = 1.0f / fmaxf(sqrtf(ss), 1e-12f);
        if (row < NP) {
            float4 o4 = make_float4(acc[i][0]*inv, acc[i][1]*inv, acc[i][2]*inv, acc[i][3]*inv);
            if (outF) *(float4*)(outF + (size_t)row*D + tc*4) = o4;
            if (outH) {
                __half2 ha = __floats2half2_rn(o4.x, o4.y);
                __half2 hb = __floats2half2_rn(o4.z, o4.w);
                uint2 u; u.x = *(unsigned*)&ha; u.y = *(unsigned*)&hb;
                *(uint2*)(outH + (size_t)row*D + tc*4) = u;
            }
        }
    }
}

// ---------------- qkv projection with fused gather ----------------
__global__ void k_qkv(const int* __restrict__ idx,
                      const float* __restrict__ W, const float* __restrict__ bias) {
    __shared__ float As[16][64];
    __shared__ float Ws[16][128];
    __shared__ int ridx[64];
    int tid = threadIdx.x;
    int tr = tid >> 5, tc = tid & 31;
    int rb = blockIdx.x * 64;        // 512 blocks  (M = 32768)
    int nb = blockIdx.y * 128;       // 3 blocks    (N = 384)
    if (tid < 64) ridx[tid] = idx[rb + tid];
    __syncthreads();
    float acc[8][4];
    #pragma unroll
    for (int i=0;i<8;i++)
        #pragma unroll
        for (int j=0;j<4;j++) acc[i][j]=0.f;

    for (int k0=0;k0<128;k0+=16) {
        {
            int m  = tid & 63;
            int kk = (tid >> 6) << 2;
            float4 v = *(const float4*)(g_enc1 + (size_t)ridx[m]*D + k0 + kk);
            As[kk][m]=v.x; As[kk+1][m]=v.y; As[kk+2][m]=v.z; As[kk+3][m]=v.w;
        }
        {
            int n  = tid & 127;
            int kk = (tid >> 7) << 3;
            float4 v  = *(const float4*)(W + (size_t)(nb+n)*D + k0 + kk);
            Ws[kk  ][n]=v.x;  Ws[kk+1][n]=v.y;  Ws[kk+2][n]=v.z;  Ws[kk+3][n]=v.w;
            float4 v2 = *(const float4*)(W + (size_t)(nb+n)*D + k0 + kk + 4);
            Ws[kk+4][n]=v2.x; Ws[kk+5][n]=v2.y; Ws[kk+6][n]=v2.z; Ws[kk+7][n]=v2.w;
        }
        __syncthreads();
        #pragma unroll
        for (int kk=0;kk<16;kk++) {
            float4 a0 = *(const float4*)&As[kk][tr*8];
            float4 a1 = *(const float4*)&As[kk][tr*8+4];
            float4 w4 = *(const float4*)&Ws[kk][tc*4];
            float a[8] = {a0.x,a0.y,a0.z,a0.w,a1.x,a1.y,a1.z,a1.w};
            float w[4] = {w4.x,w4.y,w4.z,w4.w};
            #pragma unroll
            for (int i=0;i<8;i++)
                #pragma unroll
                for (int j=0;j<4;j++)
                    acc[i][j] += a[i]*w[j];
        }
        __syncthreads();
    }
    #pragma unroll
    for (int i=0;i<8;i++) {
        int row = rb + tr*8 + i;
        int c   = nb + tc*4;
        float4 o4 = make_float4(acc[i][0]+bias[c], acc[i][1]+bias[c+1],
                                acc[i][2]+bias[c+2], acc[i][3]+bias[c+3]);
        *(float4*)(g_qkv + (size_t)row*(3*D) + c) = o4;
    }
}

// ---------------- attention per (b,h); mean-over-L folded into pbar matvec ----------------
__global__ void k_attn() {
    __shared__ float ks[64][32];
    __shared__ float vs[64][32];
    __shared__ float ps[64][65];     // padded: conflict-free column access
    __shared__ float pbar[64];
    int b = blockIdx.x, h = blockIdx.y;
    int tid = threadIdx.x;           // 256
    for (int t = tid; t < 512; t += 256) {
        int l = t >> 3, c4 = (t & 7) << 2;
        const float* base = g_qkv + (size_t)(b*LL + l)*(3*D) + h*HD + c4;
        *(float4*)&ks[l][c4] = *(const float4*)(base + 128);
        *(float4*)&vs[l][c4] = *(const float4*)(base + 256);
    }
    __syncthreads();
    {
        int i  = tid & 63;
        int jg = tid >> 6;
        float4 q[8];
        const float* qb = g_qkv + (size_t)(b*LL + i)*(3*D) + h*HD;
        #pragma unroll
        for (int u=0;u<8;u++) q[u] = *(const float4*)(qb + 4*u);
        const float scale = 0.17677669529663687f;   // 1/sqrt(32)
        #pragma unroll
        for (int jj=0;jj<16;jj++) {
            int j = jg*16 + jj;                      // warp-uniform j -> smem broadcast
            float s = 0.f;
            #pragma unroll
            for (int u=0;u<8;u++) {
                float4 kv = *(const float4*)&ks[j][4*u];
                s += q[u].x*kv.x + q[u].y*kv.y + q[u].z*kv.z + q[u].w*kv.w;
            }
            ps[i][j] = s * scale;
        }
    }
    __syncthreads();
    if (tid < 64) {
        int i = tid;
        float mx = -1e30f;
        for (int j=0;j<64;j++) mx = fmaxf(mx, ps[i][j]);
        float sum = 0.f;
        for (int j=0;j<64;j++) { float e = expf(ps[i][j]-mx); ps[i][j]=e; sum+=e; }
        float inv = 1.0f/sum;
        for (int j=0;j<64;j++) ps[i][j] *= inv;
    }
    __syncthreads();
    if (tid < 64) {
        int j = tid;
        float s = 0.f;
        for (int i=0;i<64;i++) s += ps[i][j];
        pbar[j] = s * (1.0f/64.0f);
    }
    __syncthreads();
    if (tid < 32) {
        int c = tid;
        float s = 0.f;
        #pragma unroll 4
        for (int j=0;j<64;j++) s += pbar[j]*vs[j][c];
        g_obar[(size_t)b*D + h*HD + c] = s;
    }
}

// ---------------- out-proj (after mean) + tar_embed gather ----------------
__global__ void k_out(const int* __restrict__ data_poi,
                      const float* __restrict__ Wo, const float* __restrict__ bo,
                      float* __restrict__ out) {
    __shared__ float ob[128];
    int b = blockIdx.x, r = threadIdx.x;   // 128 threads
    ob[r] = g_obar[(size_t)b*D + r];
    __syncthreads();
    float acc = bo[r];
    const float* wr = Wo + (size_t)r*D;
    #pragma unroll 8
    for (int k=0;k<D;k++) acc += ob[k]*wr[k];
    out[(size_t)b*D + r] = acc;            // aggr_feat
    int p = data_poi[b];
    out[(size_t)BB*D + (size_t)b*D + r] = g_enc1[(size_t)p*D + r];   // tar_embed
}

// ---------------- launch ----------------
extern "C" void kernel_launch(void* const* d_in, const int* in_sizes, int n_in,
                              void* d_out, int out_size) {
    const float* poi_embeds = (const float*)d_in[0];
    const int*   edges      = (const int*)  d_in[1];   // [2, NE] row-major
    const float* dvec       = (const float*)d_in[2];
    const int*   data_poi   = (const int*)  d_in[3];
    const int*   data_x     = (const int*)  d_in[4];
    const float* lin_w      = (const float*)d_in[5];   // [2,128,128]
    const float* lin_b      = (const float*)d_in[6];   // [2,128]
    const float* in_w       = (const float*)d_in[7];   // [384,128]
    const float* in_b       = (const float*)d_in[8];
    const float* out_w      = (const float*)d_in[9];   // [128,128]
    const float* out_b      = (const float*)d_in[10];
    float* out = (float*)d_out;

    float  *p_enc1;
    __half *p_ench;
    cudaGetSymbolAddress((void**)&p_enc1, g_enc1);
    cudaGetSymbolAddress((void**)&p_ench, g_ench);

    k_init<<<(NP+255)/256, 256>>>();
    k_deg <<<(NE+255)/256, 256>>>(edges);
    k_cvt <<<(NP*D/4+255)/256, 256>>>(poi_embeds, p_ench);
    k_scan<<<1, 1024>>>();
    k_fill<<<(NE+255)/256, 256>>>(edges, dvec);

    // layer 0: aggregate fp16 poi embeds -> fused linear -> fp16 enc0 (in g_ench)
    k_agg<<<(NP*32+255)/256, 256>>>(p_ench);
    k_lin<<<NPAD/64, 256>>>(lin_w, lin_b, nullptr, p_ench);
    // layer 1: aggregate fp16 enc0 -> fused linear -> fp32 enc1
    k_agg<<<(NP*32+255)/256, 256>>>(p_ench);
    k_lin<<<NPAD/64, 256>>>(lin_w + D*D, lin_b + D, p_enc1, nullptr);

    // attention block
    k_qkv<<<dim3(512,3), 256>>>(data_x, in_w, in_b);
    k_attn<<<dim3(BB, NH), 256>>>();
    k_out<<<BB, 128>>>(data_poi, out_w, out_b, out);
}

// round 3
// speedup vs baseline: 1.1662x; 1.1088x over previous
#include <cuda_runtime.h>
#include <cuda_fp16.h>
#include <math.h>

#define NP 50000
#define NPAD 50048          // 782 * 64
#define D 128
#define NE 800000
#define EC (2*NE)           // CSR entries (self loops handled analytically)
#define BB 512
#define LL 64
#define NH 4
#define HD 32
#define NBLK 196            // ceil(NP/256)

// ---------------- scratch (device globals; no allocations) ----------------
__device__ float  g_deg[NP];
__device__ int    g_ptr[NP+1];
__device__ int    g_fill[NP];
__device__ int    g_bsum[NBLK];
__device__ int    g_boff[NBLK];
__device__ int2   g_edge[EC];       // (dst, w-as-int) packed
__device__ __half g_ench[NPAD*D];   // fp16 gather operand (poi, then enc0)
__device__ float  g_enc1[NPAD*D];   // final encoder output (fp32)
__device__ float  g_agg[NPAD*D];
__device__ float  g_sumw[NPAD];
__device__ float  g_qkv[BB*LL*3*D];
__device__ float  g_obar[BB*D];

// ---------------- packed f32x2 helpers ----------------
typedef unsigned long long ull;
#define FMA_F32X2(d,a,b) asm("fma.rn.f32x2 %0, %1, %2, %0;" : "+l"(d) : "l"(a), "l"(b))
__device__ __forceinline__ ull splat2(float x) {
    ull r; asm("mov.b64 %0, {%1, %1};" : "=l"(r) : "r"(__float_as_uint(x))); return r;
}
__device__ __forceinline__ float2 unpack2(ull v) {
    unsigned lo, hi; asm("mov.b64 {%0, %1}, %2;" : "=r"(lo), "=r"(hi) : "l"(v));
    return make_float2(__uint_as_float(lo), __uint_as_float(hi));
}

// ---------------- graph prep ----------------
__global__ void k_init() {
    int i = blockIdx.x*blockDim.x + threadIdx.x;
    if (i < NP) { g_deg[i] = 1.0f; g_fill[i] = 0; }   // 1.0 = self loop
}

__global__ void k_deg(const int* __restrict__ edges) {
    int e = blockIdx.x*blockDim.x + threadIdx.x;
    if (e < NE) {
        atomicAdd(&g_deg[edges[e]],    1.0f);
        atomicAdd(&g_deg[edges[NE+e]], 1.0f);
    }
}

// ---- parallel 3-phase exclusive scan of (deg-1) -> g_ptr ----
__global__ void k_scan1() {
    __shared__ int ws[8];
    int b = blockIdx.x, t = threadIdx.x, i = b*256 + t;
    int v = (i < NP) ? (int)g_deg[i] - 1 : 0;
    #pragma unroll
    for (int o=16;o>0;o>>=1) v += __shfl_xor_sync(0xffffffffu, v, o);
    if ((t & 31) == 0) ws[t>>5] = v;
    __syncthreads();
    if (t == 0) {
        int s = 0;
        #pragma unroll
        for (int k=0;k<8;k++) s += ws[k];
        g_bsum[b] = s;
    }
}

__global__ void k_scan2() {    // 1 block, 256 threads: scan 196 block sums
    __shared__ int ws[8];
    int t = threadIdx.x, lane = t & 31, wid = t >> 5;
    int v = (t < NBLK) ? g_bsum[t] : 0;
    int x = v;
    #pragma unroll
    for (int o=1;o<32;o<<=1){ int u=__shfl_up_sync(0xffffffffu,x,o); if(lane>=o) x+=u; }
    if (lane == 31) ws[wid] = x;
    __syncthreads();
    if (wid == 0) {
        int y = (lane < 8) ? ws[lane] : 0;
        #pragma unroll
        for (int o=1;o<8;o<<=1){ int u=__shfl_up_sync(0xffffffffu,y,o); if(lane>=o) y+=u; }
        if (lane < 8) ws[lane] = y;
    }
    __syncthreads();
    int excl = x - v + (wid ? ws[wid-1] : 0);
    if (t < NBLK) g_boff[t] = excl;
    if (t == NBLK-1) g_ptr[NP] = excl + v;
}

__global__ void k_scan3() {
    __shared__ int ws[8];
    int b = blockIdx.x, t = threadIdx.x, i = b*256 + t;
    int lane = t & 31, wid = t >> 5;
    int v = (i < NP) ? (int)g_deg[i] - 1 : 0;
    int x = v;
    #pragma unroll
    for (int o=1;o<32;o<<=1){ int u=__shfl_up_sync(0xffffffffu,x,o); if(lane>=o) x+=u; }
    if (lane == 31) ws[wid] = x;
    __syncthreads();
    if (wid == 0) {
        int y = (lane < 8) ? ws[lane] : 0;
        #pragma unroll
        for (int o=1;o<8;o<<=1){ int u=__shfl_up_sync(0xffffffffu,y,o); if(lane>=o) y+=u; }
        if (lane < 8) ws[lane] = y;
    }
    __syncthreads();
    if (i < NP) g_ptr[i] = x - v + (wid ? ws[wid-1] : 0) + g_boff[b];
}

// one thread per ORIGINAL edge: w is symmetric -> fill both directions
__global__ void k_fill(const int* __restrict__ edges, const float* __restrict__ dvec) {
    int e = blockIdx.x*blockDim.x + threadIdx.x;
    if (e >= NE) return;
    int s = edges[e], d = edges[NE+e];
    float dv = dvec[e];
    float wv = rsqrtf(g_deg[s]*g_deg[d]) * expf(-dv*dv);
    int wi = __float_as_int(wv);
    int p1 = atomicAdd(&g_fill[s], 1);
    g_edge[g_ptr[s] + p1] = make_int2(d, wi);
    int p2 = atomicAdd(&g_fill[d], 1);
    g_edge[g_ptr[d] + p2] = make_int2(s, wi);
}

// fp32 -> fp16 convert (poi embeddings)
__global__ void k_cvt(const float* __restrict__ x, __half* __restrict__ y) {
    int i = (blockIdx.x*blockDim.x + threadIdx.x) * 4;
    if (i < NP*D) {
        float4 v = *(const float4*)(x + i);
        __half2 a = __floats2half2_rn(v.x, v.y);
        __half2 b = __floats2half2_rn(v.z, v.w);
        uint2 o; o.x = *(unsigned*)&a; o.y = *(unsigned*)&b;
        *(uint2*)(y + i) = o;
    }
}

// ---------------- GNN layer: aggregate fp16 enc (warp per node), fp32 accum ----------------
__global__ void k_agg(const __half* __restrict__ enc) {
    int warp = (blockIdx.x*blockDim.x + threadIdx.x) >> 5;
    int lane = threadIdx.x & 31;
    if (warp >= NP) return;
    int beg = g_ptr[warp], end = g_ptr[warp+1];
    // self loop: w = rsqrt(deg*deg)*exp(0) = 1/deg
    float wself = 1.0f / g_deg[warp];
    uint2 sv = *(const uint2*)(enc + (size_t)warp*D + lane*4);
    float2 fa = __half22float2(*(const __half2*)&sv.x);
    float2 fb = __half22float2(*(const __half2*)&sv.y);
    float4 acc = make_float4(wself*fa.x, wself*fa.y, wself*fb.x, wself*fb.y);
    float sw = wself;
    for (int i = beg; i < end; i++) {
        int2  e  = __ldg(&g_edge[i]);          // broadcast: same addr all lanes
        float wv = __int_as_float(e.y);
        uint2 v  = *(const uint2*)(enc + (size_t)e.x*D + lane*4);
        float2 va = __half22float2(*(const __half2*)&v.x);
        float2 vb = __half22float2(*(const __half2*)&v.y);
        acc.x += wv*va.x; acc.y += wv*va.y; acc.z += wv*vb.x; acc.w += wv*vb.y;
        sw += wv;
    }
    *(float4*)(g_agg + (size_t)warp*D + lane*4) = acc;
    if (lane == 0) g_sumw[warp] = sw;
}

// ---------------- fused linear + leaky + L2-normalize (f32x2 inner) ----------------
__global__ void k_lin(const float* __restrict__ W, const float* __restrict__ bias,
                      float* __restrict__ outF, __half* __restrict__ outH) {
    __shared__ float As[16][64];
    __shared__ float Ws[16][128];
    int tid = threadIdx.x;       // 256
    int tr = tid >> 5;           // warp id 0..7  -> rows tr*8 .. tr*8+7
    int tc = tid & 31;           // lane          -> cols tc*4 .. tc*4+3
    int rb = blockIdx.x * 64;
    ull accp[4][4];
    #pragma unroll
    for (int p=0;p<4;p++)
        #pragma unroll
        for (int j=0;j<4;j++) accp[p][j]=0ull;

    for (int k0=0;k0<128;k0+=16) {
        {
            int m  = tid & 63;
            int kk = (tid >> 6) << 2;
            float4 v = *(const float4*)(g_agg + (size_t)(rb+m)*D + k0 + kk);
            As[kk][m]=v.x; As[kk+1][m]=v.y; As[kk+2][m]=v.z; As[kk+3][m]=v.w;
        }
        {
            int n  = tid & 127;
            int kk = (tid >> 7) << 3;
            float4 v  = *(const float4*)(W + (size_t)n*D + k0 + kk);
            Ws[kk  ][n]=v.x;  Ws[kk+1][n]=v.y;  Ws[kk+2][n]=v.z;  Ws[kk+3][n]=v.w;
            float4 v2 = *(const float4*)(W + (size_t)n*D + k0 + kk + 4);
            Ws[kk+4][n]=v2.x; Ws[kk+5][n]=v2.y; Ws[kk+6][n]=v2.z; Ws[kk+7][n]=v2.w;
        }
        __syncthreads();
        #pragma unroll
        for (int kk=0;kk<16;kk++) {
            ulonglong2 aA = *(const ulonglong2*)&As[kk][tr*8];     // (a0,a1),(a2,a3)
            ulonglong2 aB = *(const ulonglong2*)&As[kk][tr*8+4];   // (a4,a5),(a6,a7)
            float4 w4 = *(const float4*)&Ws[kk][tc*4];
            ull wp[4] = { splat2(w4.x), splat2(w4.y), splat2(w4.z), splat2(w4.w) };
            #pragma unroll
            for (int j=0;j<4;j++) {
                FMA_F32X2(accp[0][j], aA.x, wp[j]);
                FMA_F32X2(accp[1][j], aA.y, wp[j]);
                FMA_F32X2(accp[2][j], aB.x, wp[j]);
                FMA_F32X2(accp[3][j], aB.y, wp[j]);
            }
        }
        __syncthreads();
    }
    float acc[8][4];
    #pragma unroll
    for (int p=0;p<4;p++)
        #pragma unroll
        for (int j=0;j<4;j++) {
            float2 u = unpack2(accp[p][j]);
            acc[2*p][j] = u.x; acc[2*p+1][j] = u.y;
        }
    // epilogue: bias*sumw, leaky, row L2-normalize
    #pragma unroll
    for (int i=0;i<8;i++) {
        int row = rb + tr*8 + i;
        float sw = g_sumw[row];
        float ss = 0.f;
        #pragma unroll
        for (int j=0;j<4;j++) {
            float v = acc[i][j] + bias[tc*4+j]*sw;
            v = (v >= 0.f) ? v : 0.01f*v;
            acc[i][j] = v;
            ss += v*v;
        }
        #pragma unroll
        for (int o=16;o>0;o>>=1) ss += __shfl_xor_sync(0xffffffffu, ss, o);
        float inv = 1.0f / fmaxf(sqrtf(ss), 1e-12f);
        if (row < NP) {
            float4 o4 = make_float4(acc[i][0]*inv, acc[i][1]*inv, acc[i][2]*inv, acc[i][3]*inv);
            if (outF) *(float4*)(outF + (size_t)row*D + tc*4) = o4;
            if (outH) {
                __half2 ha = __floats2half2_rn(o4.x, o4.y);
                __half2 hb = __floats2half2_rn(o4.z, o4.w);
                uint2 u; u.x = *(unsigned*)&ha; u.y = *(unsigned*)&hb;
                *(uint2*)(outH + (size_t)row*D + tc*4) = u;
            }
        }
    }
}

// ---------------- qkv projection with fused gather (f32x2 inner) ----------------
__global__ void k_qkv(const int* __restrict__ idx,
                      const float* __restrict__ W, const float* __restrict__ bias) {
    __shared__ float As[16][64];
    __shared__ float Ws[16][128];
    __shared__ int ridx[64];
    int tid = threadIdx.x;
    int tr = tid >> 5, tc = tid & 31;
    int rb = blockIdx.x * 64;        // 512 blocks  (M = 32768)
    int nb = blockIdx.y * 128;       // 3 blocks    (N = 384)
    if (tid < 64) ridx[tid] = idx[rb + tid];
    __syncthreads();
    ull accp[4][4];
    #pragma unroll
    for (int p=0;p<4;p++)
        #pragma unroll
        for (int j=0;j<4;j++) accp[p][j]=0ull;

    for (int k0=0;k0<128;k0+=16) {
        {
            int m  = tid & 63;
            int kk = (tid >> 6) << 2;
            float4 v = *(const float4*)(g_enc1 + (size_t)ridx[m]*D + k0 + kk);
            As[kk][m]=v.x; As[kk+1][m]=v.y; As[kk+2][m]=v.z; As[kk+3][m]=v.w;
        }
        {
            int n  = tid & 127;
            int kk = (tid >> 7) << 3;
            float4 v  = *(const float4*)(W + (size_t)(nb+n)*D + k0 + kk);
            Ws[kk  ][n]=v.x;  Ws[kk+1][n]=v.y;  Ws[kk+2][n]=v.z;  Ws[kk+3][n]=v.w;
            float4 v2 = *(const float4*)(W + (size_t)(nb+n)*D + k0 + kk + 4);
            Ws[kk+4][n]=v2.x; Ws[kk+5][n]=v2.y; Ws[kk+6][n]=v2.z; Ws[kk+7][n]=v2.w;
        }
        __syncthreads();
        #pragma unroll
        for (int kk=0;kk<16;kk++) {
            ulonglong2 aA = *(const ulonglong2*)&As[kk][tr*8];
            ulonglong2 aB = *(const ulonglong2*)&As[kk][tr*8+4];
            float4 w4 = *(const float4*)&Ws[kk][tc*4];
            ull wp[4] = { splat2(w4.x), splat2(w4.y), splat2(w4.z), splat2(w4.w) };
            #pragma unroll
            for (int j=0;j<4;j++) {
                FMA_F32X2(accp[0][j], aA.x, wp[j]);
                FMA_F32X2(accp[1][j], aA.y, wp[j]);
                FMA_F32X2(accp[2][j], aB.x, wp[j]);
                FMA_F32X2(accp[3][j], aB.y, wp[j]);
            }
        }
        __syncthreads();
    }
    #pragma unroll
    for (int p=0;p<4;p++) {
        #pragma unroll
        for (int jj=0;jj<2;jj++) {      // write two rows per pair
            int i  = 2*p + jj;
            int row = rb + tr*8 + i;
            int c   = nb + tc*4;
            float4 o4;
            float2 u0 = unpack2(accp[p][0]);
            float2 u1 = unpack2(accp[p][1]);
            float2 u2 = unpack2(accp[p][2]);
            float2 u3 = unpack2(accp[p][3]);
            o4.x = (jj? u0.y:u0.x) + bias[c];
            o4.y = (jj? u1.y:u1.x) + bias[c+1];
            o4.z = (jj? u2.y:u2.x) + bias[c+2];
            o4.w = (jj? u3.y:u3.x) + bias[c+3];
            *(float4*)(g_qkv + (size_t)row*(3*D) + c) = o4;
        }
    }
}

// ---------------- attention per (b,h); mean-over-L folded into pbar matvec ----------------
__global__ void k_attn() {
    __shared__ float ks[64][32];
    __shared__ float vs[64][32];
    __shared__ float ps[64][65];     // padded: conflict-free column access
    __shared__ float pbar[64];
    int b = blockIdx.x, h = blockIdx.y;
    int tid = threadIdx.x;           // 256
    for (int t = tid; t < 512; t += 256) {
        int l = t >> 3, c4 = (t & 7) << 2;
        const float* base = g_qkv + (size_t)(b*LL + l)*(3*D) + h*HD + c4;
        *(float4*)&ks[l][c4] = *(const float4*)(base + 128);
        *(float4*)&vs[l][c4] = *(const float4*)(base + 256);
    }
    __syncthreads();
    {
        int i  = tid & 63;
        int jg = tid >> 6;
        float4 q[8];
        const float* qb = g_qkv + (size_t)(b*LL + i)*(3*D) + h*HD;
        #pragma unroll
        for (int u=0;u<8;u++) q[u] = *(const float4*)(qb + 4*u);
        const float scale = 0.17677669529663687f;   // 1/sqrt(32)
        #pragma unroll
        for (int jj=0;jj<16;jj++) {
            int j = jg*16 + jj;                      // warp-uniform j -> smem broadcast
            float s = 0.f;
            #pragma unroll
            for (int u=0;u<8;u++) {
                float4 kv = *(const float4*)&ks[j][4*u];
                s += q[u].x*kv.x + q[u].y*kv.y + q[u].z*kv.z + q[u].w*kv.w;
            }
            ps[i][j] = s * scale;
        }
    }
    __syncthreads();
    if (tid < 64) {
        int i = tid;
        float mx = -1e30f;
        for (int j=0;j<64;j++) mx = fmaxf(mx, ps[i][j]);
        float sum = 0.f;
        for (int j=0;j<64;j++) { float e = expf(ps[i][j]-mx); ps[i][j]=e; sum+=e; }
        float inv = 1.0f/sum;
        for (int j=0;j<64;j++) ps[i][j] *= inv;
    }
    __syncthreads();
    if (tid < 64) {
        int j = tid;
        float s = 0.f;
        for (int i=0;i<64;i++) s += ps[i][j];
        pbar[j] = s * (1.0f/64.0f);
    }
    __syncthreads();
    if (tid < 32) {
        int c = tid;
        float s = 0.f;
        #pragma unroll 4
        for (int j=0;j<64;j++) s += pbar[j]*vs[j][c];
        g_obar[(size_t)b*D + h*HD + c] = s;
    }
}

// ---------------- out-proj (after mean) + tar_embed gather ----------------
__global__ void k_out(const int* __restrict__ data_poi,
                      const float* __restrict__ Wo, const float* __restrict__ bo,
                      float* __restrict__ out) {
    __shared__ float ob[128];
    int b = blockIdx.x, r = threadIdx.x;   // 128 threads
    ob[r] = g_obar[(size_t)b*D + r];
    __syncthreads();
    float acc = bo[r];
    const float* wr = Wo + (size_t)r*D;
    #pragma unroll 8
    for (int k=0;k<D;k++) acc += ob[k]*wr[k];
    out[(size_t)b*D + r] = acc;            // aggr_feat
    int p = data_poi[b];
    out[(size_t)BB*D + (size_t)b*D + r] = g_enc1[(size_t)p*D + r];   // tar_embed
}

// ---------------- launch ----------------
extern "C" void kernel_launch(void* const* d_in, const int* in_sizes, int n_in,
                              void* d_out, int out_size) {
    const float* poi_embeds = (const float*)d_in[0];
    const int*   edges      = (const int*)  d_in[1];   // [2, NE] row-major
    const float* dvec       = (const float*)d_in[2];
    const int*   data_poi   = (const int*)  d_in[3];
    const int*   data_x     = (const int*)  d_in[4];
    const float* lin_w      = (const float*)d_in[5];   // [2,128,128]
    const float* lin_b      = (const float*)d_in[6];   // [2,128]
    const float* in_w       = (const float*)d_in[7];   // [384,128]
    const float* in_b       = (const float*)d_in[8];
    const float* out_w      = (const float*)d_in[9];   // [128,128]
    const float* out_b      = (const float*)d_in[10];
    float* out = (float*)d_out;

    float  *p_enc1;
    __half *p_ench;
    cudaGetSymbolAddress((void**)&p_enc1, g_enc1);
    cudaGetSymbolAddress((void**)&p_ench, g_ench);

    k_init<<<(NP+255)/256, 256>>>();
    k_deg <<<(NE+255)/256, 256>>>(edges);
    k_cvt <<<(NP*D/4+255)/256, 256>>>(poi_embeds, p_ench);
    k_scan1<<<NBLK, 256>>>();
    k_scan2<<<1, 256>>>();
    k_scan3<<<NBLK, 256>>>();
    k_fill<<<(NE+255)/256, 256>>>(edges, dvec);

    // layer 0: aggregate fp16 poi embeds -> fused linear -> fp16 enc0 (in g_ench)
    k_agg<<<(NP*32+255)/256, 256>>>(p_ench);
    k_lin<<<NPAD/64, 256>>>(lin_w, lin_b, nullptr, p_ench);
    // layer 1: aggregate fp16 enc0 -> fused linear -> fp32 enc1
    k_agg<<<(NP*32+255)/256, 256>>>(p_ench);
    k_lin<<<NPAD/64, 256>>>(lin_w + D*D, lin_b + D, p_enc1, nullptr);

    // attention block
    k_qkv<<<dim3(512,3), 256>>>(data_x, in_w, in_b);
    k_attn<<<dim3(BB, NH), 256>>>();
    k_out<<<BB, 128>>>(data_poi, out_w, out_b, out);
}